// round 4
// baseline (speedup 1.0000x reference)
#include <cuda_runtime.h>
#include <cuda_bf16.h>
#include <mma.h>
#include <cstdint>

using namespace nvcuda;

// Fixed shapes from reference setup_inputs
#define B_      2
#define L_      512
#define D_      256
#define TILE    64            // 64x64 output tile per CTA
#define THREADS 256
#define SST     264           // smem row stride in bf16 elems: 256 + 8 pad

// smem partition (bf16 elem offsets into dynamic smem)
#define TILE_ELEMS (TILE * SST)          // 16896
#define SMEM_BYTES (4 * TILE_ELEMS * 2)  // 135168

// out[b,i,j] = sum_d x[b,i,d]*w1[d]*x[b,j,d] + bias
// (antisymmetric lin_i - lin_j cancels under (P+P^T)/2; bilinear term is
//  symmetric; w2 = W[D:,0] is dead.)
// Precision: split-bf16 3-product: a = ahi+alo, x = xhi+xlo,
//   a*x ≈ ahi*xhi + ahi*xlo + alo*xhi   (rel err ~2^-18)
__global__ __launch_bounds__(THREADS, 1)
void fused_pairwise_kernel(const float* __restrict__ x,
                           const float* __restrict__ W,
                           const float* __restrict__ bias_p,
                           float* __restrict__ out) {
    extern __shared__ __align__(16) __nv_bfloat16 smem[];
    __nv_bfloat16* sAhi = smem;
    __nv_bfloat16* sAlo = smem + TILE_ELEMS;
    __nv_bfloat16* sBhi = smem + 2 * TILE_ELEMS;
    __nv_bfloat16* sBlo = smem + 3 * TILE_ELEMS;

    const int bz  = blockIdx.z;
    const int ti  = blockIdx.y;
    const int tj  = blockIdx.x;
    const int tid = threadIdx.x;
    const int warp = tid >> 5;
    const int wr = warp >> 2;     // 0..1 : 32-row band
    const int wc = warp & 3;      // 0..3 : 16-col band

    const float4* A4 = (const float4*)(x + (size_t)(bz * L_ + ti * TILE) * D_);
    const float4* B4 = (const float4*)(x + (size_t)(bz * L_ + tj * TILE) * D_);
    const float4* W4 = (const float4*)W;   // W[:256] = w1

    // ---- stage ALL gmem loads first: 64 rows x 64 float4 per matrix ----
    // per thread: 16 float4 from A, 16 from B (lin = i*256+tid)
    float4 ra[16], rb[16];
    #pragma unroll
    for (int i = 0; i < 16; i++) {
        int lin = i * THREADS + tid;
        int row = lin >> 6;          // 0..63
        int c4  = lin & 63;          // 0..63 (float4 index within row)
        ra[i] = A4[row * 64 + c4];
        rb[i] = B4[row * 64 + c4];
    }

    // ---- convert + STS (split bf16) ----
    #pragma unroll
    for (int i = 0; i < 16; i++) {
        int lin = i * THREADS + tid;
        int row = lin >> 6;
        int c4  = lin & 63;
        float4 wv = __ldg(&W4[c4]);

        float av[4] = {ra[i].x, ra[i].y, ra[i].z, ra[i].w};
        float bv[4] = {rb[i].x, rb[i].y, rb[i].z, rb[i].w};
        float wa[4] = {wv.x, wv.y, wv.z, wv.w};

        __nv_bfloat16 ah[4], al[4], bh[4], bl[4];
        #pragma unroll
        for (int j = 0; j < 4; j++) {
            float a = av[j] * wa[j];
            ah[j] = __float2bfloat16(a);
            al[j] = __float2bfloat16(a - __bfloat162float(ah[j]));
            bh[j] = __float2bfloat16(bv[j]);
            bl[j] = __float2bfloat16(bv[j] - __bfloat162float(bh[j]));
        }
        int off = row * SST + c4 * 4;       // 8B-aligned
        *(uint2*)&sAhi[off] = *(uint2*)ah;
        *(uint2*)&sAlo[off] = *(uint2*)al;
        *(uint2*)&sBhi[off] = *(uint2*)bh;
        *(uint2*)&sBlo[off] = *(uint2*)bl;
    }
    __syncthreads();

    // ---- 48 uninterrupted wmma k-steps ----
    wmma::fragment<wmma::accumulator, 16, 16, 16, float> acc[2];
    wmma::fill_fragment(acc[0], 0.0f);
    wmma::fill_fragment(acc[1], 0.0f);

    const __nv_bfloat16* pa[3] = {sAhi, sAhi, sAlo};
    const __nv_bfloat16* pb[3] = {sBhi, sBlo, sBhi};

    #pragma unroll
    for (int p = 0; p < 3; p++) {
        const __nv_bfloat16* Abase = pa[p] + (wr * 32) * SST;
        const __nv_bfloat16* Bbase = pb[p] + (wc * 16) * SST;
        #pragma unroll
        for (int kk = 0; kk < D_; kk += 16) {
            wmma::fragment<wmma::matrix_a, 16, 16, 16, __nv_bfloat16, wmma::row_major> af0, af1;
            wmma::fragment<wmma::matrix_b, 16, 16, 16, __nv_bfloat16, wmma::col_major> bf;
            wmma::load_matrix_sync(af0, Abase + kk, SST);
            wmma::load_matrix_sync(af1, Abase + 16 * SST + kk, SST);
            wmma::load_matrix_sync(bf,  Bbase + kk, SST);
            wmma::mma_sync(acc[0], af0, bf, acc[0]);
            wmma::mma_sync(acc[1], af1, bf, acc[1]);
        }
    }

    // ---- epilogue ----
    const float bias = bias_p[0];
    #pragma unroll
    for (int r = 0; r < 2; r++) {
        #pragma unroll
        for (int t = 0; t < acc[r].num_elements; t++)
            acc[r].x[t] += bias;
        int gi = ti * TILE + wr * 32 + r * 16;
        int gj = tj * TILE + wc * 16;
        float* dst = out + (size_t)bz * L_ * L_ + (size_t)gi * L_ + gj;
        wmma::store_matrix_sync(dst, acc[r], L_, wmma::mem_row_major);
    }
}

// ---------------------------------------------------------------------------
// d_in[0] = inputs f32 (2,512,256), d_in[1] = W f32 (512,1), d_in[2] = b f32 (1,)
// d_out   = f32 (2,512,512,1)
// ---------------------------------------------------------------------------
extern "C" void kernel_launch(void* const* d_in, const int* in_sizes, int n_in,
                              void* d_out, int out_size) {
    const float* x    = (const float*)d_in[0];
    const float* W    = (const float*)d_in[1];
    const float* bptr = (const float*)d_in[2];
    float* out = (float*)d_out;

    static bool attr_set = false;
    if (!attr_set) {
        cudaFuncSetAttribute(fused_pairwise_kernel,
                             cudaFuncAttributeMaxDynamicSharedMemorySize, SMEM_BYTES);
        attr_set = true;
    }

    dim3 grid(L_ / TILE, L_ / TILE, B_);   // (8, 8, 2) = 128 CTAs
    fused_pairwise_kernel<<<grid, THREADS, SMEM_BYTES>>>(x, W, bptr, out);
}